// round 8
// baseline (speedup 1.0000x reference)
#include <cuda_runtime.h>
#include <cuda_bf16.h>
#include <cstdint>

// ---------------- problem constants ----------------
#define B_SZ 16384
#define P_N  128
#define V_N  128
#define W_N  64
#define BN_EPS 1e-5

// ---------------- scratch (static device globals; no allocation) ----------------
__device__ float   g_p[P_N * B_SZ];          // p[pathway][batch], 8 MB
__device__ double  g_S1[P_N], g_S2[P_N];

__device__ __forceinline__ uint32_t smem_u32(const void* p) {
    uint32_t a;
    asm("{ .reg .u64 t; cvta.to.shared.u64 t, %1; cvt.u32.u64 %0, t; }" : "=r"(a) : "l"(p));
    return a;
}

// swizzled byte offset inside a [rows][128 bf16] tile (256 B per row)
__device__ __forceinline__ int swz(int row, int byte_in_row) {
    return row * 256 + (byte_in_row ^ ((row & 7) << 4));
}

__device__ __forceinline__ void ldmatrix_x4(uint32_t& r0, uint32_t& r1, uint32_t& r2, uint32_t& r3,
                                            uint32_t addr) {
    asm volatile("ldmatrix.sync.aligned.m8n8.x4.shared.b16 {%0,%1,%2,%3}, [%4];"
                 : "=r"(r0), "=r"(r1), "=r"(r2), "=r"(r3) : "r"(addr));
}

__device__ __forceinline__ void mma_bf16(float& c0, float& c1, float& c2, float& c3,
                                         uint32_t a0, uint32_t a1, uint32_t a2, uint32_t a3,
                                         uint32_t b0, uint32_t b1) {
    asm volatile("mma.sync.aligned.m16n8k16.row.col.f32.bf16.bf16.f32 "
                 "{%0,%1,%2,%3}, {%4,%5,%6,%7}, {%8,%9}, {%0,%1,%2,%3};"
                 : "+f"(c0), "+f"(c1), "+f"(c2), "+f"(c3)
                 : "r"(a0), "r"(a1), "r"(a2), "r"(a3), "r"(b0), "r"(b1));
}

// ============ K1: per-pathway [128x64x128] bf16 mma.sync + fused leaky/W2/leaky ============
// grid (B/128, P), 256 threads (8 warps). Warp w: rows m0 = 16*w.
// W1 is read as fp32 directly (L2-resident) and converted to bf16 inline while staging.
__global__ __launch_bounds__(256, 4) void k1_mma(const float* __restrict__ x,
                                                 const float* __restrict__ W1,
                                                 const float* __restrict__ W2) {
    extern __shared__ char smem[];                 // [0,32768) xs swizzled, [32768,49152) ws swizzled
    const uint32_t sb = smem_u32(smem);
    const int tid = threadIdx.x;
    const int wid = tid >> 5;
    const int lid = tid & 31;
    const int rb = blockIdx.x;                     // 128-row batch block
    const int p  = blockIdx.y;                     // pathway

    // ---- load + convert x tile: 128 rows x 128 fp32 -> bf16 swizzled smem ----
    {
        const float* xrow = x + (size_t)rb * 128 * (P_N * V_N) + (size_t)p * V_N;
        #pragma unroll
        for (int i = 0; i < 16; i++) {
            int idx = tid + i * 256;               // < 4096
            int r = idx >> 5;
            int c = (idx & 31);                    // float4 index in row
            float4 v = *reinterpret_cast<const float4*>(xrow + (size_t)r * (P_N * V_N) + c * 4);
            __nv_bfloat162 lo = __float22bfloat162_rn(make_float2(v.x, v.y));
            __nv_bfloat162 hi = __float22bfloat162_rn(make_float2(v.z, v.w));
            uint2 pack = make_uint2(*reinterpret_cast<uint32_t*>(&lo), *reinterpret_cast<uint32_t*>(&hi));
            *reinterpret_cast<uint2*>(smem + swz(r, c * 8)) = pack;
        }
    }
    // ---- load + convert W1 tile: 64 rows x 128 fp32 -> bf16 swizzled smem ----
    {
        const float* wsrc = W1 + (size_t)p * (W_N * V_N);
        #pragma unroll
        for (int i = 0; i < 4; i++) {
            int idx = tid + i * 256;               // < 1024 16B-dst-chunks (8 bf16 = 8 fp32 src)
            int n = idx >> 4;
            int kc = idx & 15;
            const float4* src = reinterpret_cast<const float4*>(wsrc + n * V_N + kc * 8);
            float4 v0 = src[0], v1 = src[1];
            __nv_bfloat162 q0 = __float22bfloat162_rn(make_float2(v0.x, v0.y));
            __nv_bfloat162 q1 = __float22bfloat162_rn(make_float2(v0.z, v0.w));
            __nv_bfloat162 q2 = __float22bfloat162_rn(make_float2(v1.x, v1.y));
            __nv_bfloat162 q3 = __float22bfloat162_rn(make_float2(v1.z, v1.w));
            uint4 pack = make_uint4(*reinterpret_cast<uint32_t*>(&q0),
                                    *reinterpret_cast<uint32_t*>(&q1),
                                    *reinterpret_cast<uint32_t*>(&q2),
                                    *reinterpret_cast<uint32_t*>(&q3));
            *reinterpret_cast<uint4*>(smem + 32768 + swz(n, kc * 16)) = pack;
        }
    }
    __syncthreads();

    // ---- mainloop: warp computes [16 x 64], K=128 ----
    float acc[8][4];
    #pragma unroll
    for (int t = 0; t < 8; t++)
        #pragma unroll
        for (int j = 0; j < 4; j++) acc[t][j] = 0.f;

    const int m0 = wid * 16;
    const uint32_t a_row = m0 + (lid & 15);
    const uint32_t a_chunk = (lid >> 4) * 16;
    const int bg = lid >> 3;                        // 0..3 address group
    const int b_nrow_off = (lid & 7) + ((bg >= 2) ? 8 : 0);
    const int b_koff = (bg & 1) * 16;

    #pragma unroll
    for (int ks = 0; ks < 8; ks++) {
        const int kb = ks * 32;                     // byte offset of k-step in row
        uint32_t a0, a1, a2, a3;
        ldmatrix_x4(a0, a1, a2, a3, sb + swz(a_row, kb + a_chunk));
        #pragma unroll
        for (int t = 0; t < 4; t++) {
            uint32_t b0, b1, b2, b3;
            ldmatrix_x4(b0, b1, b2, b3,
                        sb + 32768 + swz(t * 16 + b_nrow_off, kb + b_koff));
            mma_bf16(acc[2*t][0], acc[2*t][1], acc[2*t][2], acc[2*t][3],
                     a0, a1, a2, a3, b0, b1);
            mma_bf16(acc[2*t+1][0], acc[2*t+1][1], acc[2*t+1][2], acc[2*t+1][3],
                     a0, a1, a2, a3, b2, b3);
        }
    }

    // ---- epilogue: h=leaky(acc); dot with W2 over n; p=leaky(dot) ----
    {
        const float2* w2p = reinterpret_cast<const float2*>(W2 + (size_t)p * W_N);
        float sum0 = 0.f, sum1 = 0.f;               // rows (lid>>2), (lid>>2)+8
        #pragma unroll
        for (int t = 0; t < 8; t++) {
            float2 w2v = __ldg(&w2p[t * 4 + (lid & 3)]);   // cols t*8 + (lid&3)*2, +1
            float h;
            h = acc[t][0]; h = (h >= 0.f) ? h : 0.2f * h; sum0 += h * w2v.x;
            h = acc[t][1]; h = (h >= 0.f) ? h : 0.2f * h; sum0 += h * w2v.y;
            h = acc[t][2]; h = (h >= 0.f) ? h : 0.2f * h; sum1 += h * w2v.x;
            h = acc[t][3]; h = (h >= 0.f) ? h : 0.2f * h; sum1 += h * w2v.y;
        }
        sum0 += __shfl_xor_sync(0xFFFFFFFF, sum0, 1);
        sum0 += __shfl_xor_sync(0xFFFFFFFF, sum0, 2);
        sum1 += __shfl_xor_sync(0xFFFFFFFF, sum1, 1);
        sum1 += __shfl_xor_sync(0xFFFFFFFF, sum1, 2);
        if ((lid & 3) == 0) {
            int row = lid >> 2;
            float pv0 = (sum0 >= 0.f) ? sum0 : 0.2f * sum0;
            float pv1 = (sum1 >= 0.f) ? sum1 : 0.2f * sum1;
            float* dst = g_p + (size_t)p * B_SZ + rb * 128 + m0;
            dst[row] = pv0;
            dst[row + 8] = pv1;
        }
    }
}

// ============ K2a: per-pathway sum / sumsq (fp32 lane accumulators, fp64 tree) ============
__global__ __launch_bounds__(256) void k2a_reduce() {
    const int p = blockIdx.x;
    const int tid = threadIdx.x;
    const float4* col = reinterpret_cast<const float4*>(g_p + (size_t)p * B_SZ);
    // 4 independent fp32 accumulator pairs (per float4 lane) -> short dep chains, fast FMA pipe
    float ax = 0.f, ay = 0.f, az = 0.f, aw = 0.f;
    float qx = 0.f, qy = 0.f, qz = 0.f, qw = 0.f;
    #pragma unroll 8
    for (int i = tid; i < B_SZ / 4; i += 256) {
        float4 v = col[i];
        ax += v.x; ay += v.y; az += v.z; aw += v.w;
        qx = fmaf(v.x, v.x, qx); qy = fmaf(v.y, v.y, qy);
        qz = fmaf(v.z, v.z, qz); qw = fmaf(v.w, v.w, qw);
    }
    double a1 = (double)ax + (double)ay + (double)az + (double)aw;
    double a2 = (double)qx + (double)qy + (double)qz + (double)qw;
    __shared__ double s1[256], s2[256];
    s1[tid] = a1; s2[tid] = a2;
    __syncthreads();
    for (int o = 128; o > 0; o >>= 1) {
        if (tid < o) { s1[tid] += s1[tid + o]; s2[tid] += s2[tid + o]; }
        __syncthreads();
    }
    if (tid == 0) { g_S1[p] = s1[0]; g_S2[p] = s2[0]; }
}

// ============ K3: per-block BN/L2/projection finalize + out[b] = sigmoid(dot + c) ============
// 131072 threads; thread (q = gid&31 -> 4 pathways, t = gid>>5 -> b-group of 4): 4 float4
// loads, butterfly over 32 lanes, lane q==0 writes float4 of sigmoids.
__global__ __launch_bounds__(256) void k3_out(float* __restrict__ out,
                                              const float* __restrict__ gamma,
                                              const float* __restrict__ beta,
                                              const float* __restrict__ Wd,
                                              const float* __restrict__ bdp) {
    __shared__ float sa[128];        // final coefficient per pathway
    __shared__ float sw[128];        // scratch: g*wd*inv_sigma
    __shared__ float sn[128], st[128];
    __shared__ float sc_s;
    const int tid = threadIdx.x;

    // ---- in-block finalize (threads 0..127) ----
    if (tid < 128) {
        const int p = tid;
        const double invB = 1.0 / (double)B_SZ;
        double mean_d = g_S1[p] * invB;
        double var_d = g_S2[p] * invB - mean_d * mean_d;   // fp64: cancellation-sensitive
        float var = (float)(var_d < 0.0 ? 0.0 : var_d);
        float mean = (float)mean_d;
        float sig2 = var + (float)BN_EPS;
        float inv_sigma = rsqrtf(sig2);
        float g = gamma[p], bt = beta[p], wd = Wd[p];
        sn[p] = g * g * (float)B_SZ * var / sig2 + (float)B_SZ * bt * bt;
        st[p] = (bt - mean * g * inv_sigma) * wd;
        sw[p] = g * wd * inv_sigma;
    }
    __syncthreads();
    for (int o = 64; o > 0; o >>= 1) {
        if (tid < o) { sn[tid] += sn[tid + o]; st[tid] += st[tid + o]; }
        __syncthreads();
    }
    if (tid < 128) {
        float inv_norm = rsqrtf(sn[0]);
        sa[tid] = sw[tid] * inv_norm;
        if (tid == 0) sc_s = st[0] * inv_norm + bdp[0];
    }
    __syncthreads();
    const float sc = sc_s;

    // ---- dot + sigmoid ----
    const int gid = blockIdx.x * 256 + tid;
    const int q = gid & 31;                // pathway chunk (4 pathways)
    const int t = gid >> 5;                // float4 index over b (0..4095)
    const float4* pp = reinterpret_cast<const float4*>(g_p);

    float4 acc = make_float4(0.f, 0.f, 0.f, 0.f);
    #pragma unroll
    for (int i = 0; i < 4; i++) {
        int p = q * 4 + i;
        float4 v = pp[(size_t)p * (B_SZ / 4) + t];
        float a = sa[p];
        acc.x += v.x * a; acc.y += v.y * a; acc.z += v.z * a; acc.w += v.w * a;
    }
    #pragma unroll
    for (int m = 1; m < 32; m <<= 1) {
        acc.x += __shfl_xor_sync(0xFFFFFFFF, acc.x, m);
        acc.y += __shfl_xor_sync(0xFFFFFFFF, acc.y, m);
        acc.z += __shfl_xor_sync(0xFFFFFFFF, acc.z, m);
        acc.w += __shfl_xor_sync(0xFFFFFFFF, acc.w, m);
    }
    if (q == 0) {
        float4 o;
        o.x = 1.f / (1.f + expf(-(acc.x + sc)));
        o.y = 1.f / (1.f + expf(-(acc.y + sc)));
        o.z = 1.f / (1.f + expf(-(acc.z + sc)));
        o.w = 1.f / (1.f + expf(-(acc.w + sc)));
        reinterpret_cast<float4*>(out)[t] = o;
    }
}

// ============ launch ============
extern "C" void kernel_launch(void* const* d_in, const int* in_sizes, int n_in,
                              void* d_out, int out_size) {
    const float* x     = (const float*)d_in[0];
    const float* W1    = (const float*)d_in[1];
    const float* W2    = (const float*)d_in[2];
    const float* gamma = (const float*)d_in[3];
    const float* beta  = (const float*)d_in[4];
    const float* Wd    = (const float*)d_in[5];
    const float* bdp   = (const float*)d_in[6];
    float* out = (float*)d_out;

    k1_mma<<<dim3(B_SZ / 128, P_N), 256, 49152>>>(x, W1, W2);
    k2a_reduce<<<P_N, 256>>>();
    k3_out<<<512, 256>>>(out, gamma, beta, Wd, bdp);
}

// round 9
// speedup vs baseline: 1.1446x; 1.1446x over previous
#include <cuda_runtime.h>
#include <cuda_bf16.h>
#include <cstdint>

// ---------------- problem constants ----------------
#define B_SZ 16384
#define P_N  128
#define V_N  128
#define W_N  64
#define BN_EPS 1e-5

// ---------------- scratch (static device globals; no allocation) ----------------
__device__ float          g_p[P_N * B_SZ];          // p[pathway][batch], 8 MB
__device__ __nv_bfloat16  g_W1bf[P_N * W_N * V_N];  // bf16 W1, row-major [p][w][v], 2 MB
__device__ double         g_S1[P_N], g_S2[P_N];

__device__ __forceinline__ uint32_t smem_u32(const void* p) {
    uint32_t a;
    asm("{ .reg .u64 t; cvta.to.shared.u64 t, %1; cvt.u32.u64 %0, t; }" : "=r"(a) : "l"(p));
    return a;
}

// swizzled byte offset inside a [rows][128 bf16] tile (256 B per row)
__device__ __forceinline__ int swz(int row, int byte_in_row) {
    return row * 256 + (byte_in_row ^ ((row & 7) << 4));
}

__device__ __forceinline__ void ldmatrix_x4(uint32_t& r0, uint32_t& r1, uint32_t& r2, uint32_t& r3,
                                            uint32_t addr) {
    asm volatile("ldmatrix.sync.aligned.m8n8.x4.shared.b16 {%0,%1,%2,%3}, [%4];"
                 : "=r"(r0), "=r"(r1), "=r"(r2), "=r"(r3) : "r"(addr));
}

__device__ __forceinline__ void mma_bf16(float& c0, float& c1, float& c2, float& c3,
                                         uint32_t a0, uint32_t a1, uint32_t a2, uint32_t a3,
                                         uint32_t b0, uint32_t b1) {
    asm volatile("mma.sync.aligned.m16n8k16.row.col.f32.bf16.bf16.f32 "
                 "{%0,%1,%2,%3}, {%4,%5,%6,%7}, {%8,%9}, {%0,%1,%2,%3};"
                 : "+f"(c0), "+f"(c1), "+f"(c2), "+f"(c3)
                 : "r"(a0), "r"(a1), "r"(a2), "r"(a3), "r"(b0), "r"(b1));
}

// ============ K0: convert W1 fp32 -> bf16 row-major ============
__global__ __launch_bounds__(256) void k0_w1bf(const float* __restrict__ W1) {
    int idx = blockIdx.x * 256 + threadIdx.x;      // < 262144, each handles 4 elems
    float4 v = *reinterpret_cast<const float4*>(W1 + (size_t)idx * 4);
    __nv_bfloat162 lo = __float22bfloat162_rn(make_float2(v.x, v.y));
    __nv_bfloat162 hi = __float22bfloat162_rn(make_float2(v.z, v.w));
    uint2 pack = make_uint2(*reinterpret_cast<uint32_t*>(&lo), *reinterpret_cast<uint32_t*>(&hi));
    *reinterpret_cast<uint2*>(g_W1bf + (size_t)idx * 4) = pack;
}

// ============ K1: per-pathway [128x64x128] bf16 mma.sync, 4 warps x (32x64) tiles ============
// grid (B/128, P), 128 threads (4 warps). Warp w: rows m0 = 32*w.
// Wider warp tile halves the ldmatrix-B redundancy (L1tex was the R8 bottleneck at 81.6%).
__global__ __launch_bounds__(128, 4) void k1_mma(const float* __restrict__ x,
                                                 const float* __restrict__ W2) {
    extern __shared__ char smem[];                 // [0,32768) xs swizzled, [32768,49152) ws swizzled
    const uint32_t sb = smem_u32(smem);
    const int tid = threadIdx.x;
    const int wid = tid >> 5;
    const int lid = tid & 31;
    const int rb = blockIdx.x;                     // 128-row batch block
    const int p  = blockIdx.y;                     // pathway

    // ---- load + convert x tile: 128 rows x 128 fp32 -> bf16 swizzled smem ----
    {
        const float* xrow = x + (size_t)rb * 128 * (P_N * V_N) + (size_t)p * V_N;
        #pragma unroll
        for (int i = 0; i < 32; i++) {
            int idx = tid + i * 128;               // < 4096
            int r = idx >> 5;
            int c = (idx & 31);                    // float4 index in row
            float4 v = *reinterpret_cast<const float4*>(xrow + (size_t)r * (P_N * V_N) + c * 4);
            __nv_bfloat162 lo = __float22bfloat162_rn(make_float2(v.x, v.y));
            __nv_bfloat162 hi = __float22bfloat162_rn(make_float2(v.z, v.w));
            uint2 pack = make_uint2(*reinterpret_cast<uint32_t*>(&lo), *reinterpret_cast<uint32_t*>(&hi));
            *reinterpret_cast<uint2*>(smem + swz(r, c * 8)) = pack;
        }
    }
    // ---- copy W1 bf16 tile: 64 rows x 128 -> swizzled smem ----
    {
        const uint4* wsrc = reinterpret_cast<const uint4*>(g_W1bf + (size_t)p * (W_N * V_N));
        #pragma unroll
        for (int i = 0; i < 8; i++) {
            int idx = tid + i * 128;               // < 1024 16B-chunks
            int n = idx >> 4;
            int kc = idx & 15;
            *reinterpret_cast<uint4*>(smem + 32768 + swz(n, kc * 16)) = wsrc[idx];
        }
    }
    __syncthreads();

    // ---- mainloop: warp computes [32 x 64], K=128 ----
    float acc[2][8][4];                             // [m16-frag][n8-frag][quad]
    #pragma unroll
    for (int m = 0; m < 2; m++)
        #pragma unroll
        for (int t = 0; t < 8; t++)
            #pragma unroll
            for (int j = 0; j < 4; j++) acc[m][t][j] = 0.f;

    const int m0 = wid * 32;
    const uint32_t a_row = m0 + (lid & 15);
    const uint32_t a_chunk = (lid >> 4) * 16;
    const int bg = lid >> 3;                        // 0..3 address group
    const int b_nrow_off = (lid & 7) + ((bg >= 2) ? 8 : 0);
    const int b_koff = (bg & 1) * 16;

    #pragma unroll
    for (int ks = 0; ks < 8; ks++) {
        const int kb = ks * 32;                     // byte offset of k-step in row
        uint32_t a00, a01, a02, a03;                // rows [m0, m0+16)
        uint32_t a10, a11, a12, a13;                // rows [m0+16, m0+32)
        ldmatrix_x4(a00, a01, a02, a03, sb + swz(a_row, kb + a_chunk));
        ldmatrix_x4(a10, a11, a12, a13, sb + swz(a_row + 16, kb + a_chunk));
        #pragma unroll
        for (int t = 0; t < 4; t++) {
            uint32_t b0, b1, b2, b3;
            ldmatrix_x4(b0, b1, b2, b3,
                        sb + 32768 + swz(t * 16 + b_nrow_off, kb + b_koff));
            mma_bf16(acc[0][2*t][0], acc[0][2*t][1], acc[0][2*t][2], acc[0][2*t][3],
                     a00, a01, a02, a03, b0, b1);
            mma_bf16(acc[0][2*t+1][0], acc[0][2*t+1][1], acc[0][2*t+1][2], acc[0][2*t+1][3],
                     a00, a01, a02, a03, b2, b3);
            mma_bf16(acc[1][2*t][0], acc[1][2*t][1], acc[1][2*t][2], acc[1][2*t][3],
                     a10, a11, a12, a13, b0, b1);
            mma_bf16(acc[1][2*t+1][0], acc[1][2*t+1][1], acc[1][2*t+1][2], acc[1][2*t+1][3],
                     a10, a11, a12, a13, b2, b3);
        }
    }

    // ---- epilogue: h=leaky(acc); dot with W2 over n; p=leaky(dot) ----
    {
        const float2* w2p = reinterpret_cast<const float2*>(W2 + (size_t)p * W_N);
        float s00 = 0.f, s01 = 0.f;                 // m-frag 0: rows (lid>>2), (lid>>2)+8
        float s10 = 0.f, s11 = 0.f;                 // m-frag 1: +16
        #pragma unroll
        for (int t = 0; t < 8; t++) {
            float2 w2v = __ldg(&w2p[t * 4 + (lid & 3)]);   // cols t*8 + (lid&3)*2, +1
            float h;
            h = acc[0][t][0]; h = (h >= 0.f) ? h : 0.2f * h; s00 += h * w2v.x;
            h = acc[0][t][1]; h = (h >= 0.f) ? h : 0.2f * h; s00 += h * w2v.y;
            h = acc[0][t][2]; h = (h >= 0.f) ? h : 0.2f * h; s01 += h * w2v.x;
            h = acc[0][t][3]; h = (h >= 0.f) ? h : 0.2f * h; s01 += h * w2v.y;
            h = acc[1][t][0]; h = (h >= 0.f) ? h : 0.2f * h; s10 += h * w2v.x;
            h = acc[1][t][1]; h = (h >= 0.f) ? h : 0.2f * h; s10 += h * w2v.y;
            h = acc[1][t][2]; h = (h >= 0.f) ? h : 0.2f * h; s11 += h * w2v.x;
            h = acc[1][t][3]; h = (h >= 0.f) ? h : 0.2f * h; s11 += h * w2v.y;
        }
        s00 += __shfl_xor_sync(0xFFFFFFFF, s00, 1);
        s00 += __shfl_xor_sync(0xFFFFFFFF, s00, 2);
        s01 += __shfl_xor_sync(0xFFFFFFFF, s01, 1);
        s01 += __shfl_xor_sync(0xFFFFFFFF, s01, 2);
        s10 += __shfl_xor_sync(0xFFFFFFFF, s10, 1);
        s10 += __shfl_xor_sync(0xFFFFFFFF, s10, 2);
        s11 += __shfl_xor_sync(0xFFFFFFFF, s11, 1);
        s11 += __shfl_xor_sync(0xFFFFFFFF, s11, 2);
        if ((lid & 3) == 0) {
            int row = lid >> 2;
            float pv00 = (s00 >= 0.f) ? s00 : 0.2f * s00;
            float pv01 = (s01 >= 0.f) ? s01 : 0.2f * s01;
            float pv10 = (s10 >= 0.f) ? s10 : 0.2f * s10;
            float pv11 = (s11 >= 0.f) ? s11 : 0.2f * s11;
            float* dst = g_p + (size_t)p * B_SZ + rb * 128 + m0;
            dst[row] = pv00;
            dst[row + 8] = pv01;
            dst[row + 16] = pv10;
            dst[row + 24] = pv11;
        }
    }
}

// ============ K2a: per-pathway sum / sumsq (fp32 lane accumulators, fp64 tree) ============
__global__ __launch_bounds__(256) void k2a_reduce() {
    const int p = blockIdx.x;
    const int tid = threadIdx.x;
    const float4* col = reinterpret_cast<const float4*>(g_p + (size_t)p * B_SZ);
    float ax = 0.f, ay = 0.f, az = 0.f, aw = 0.f;
    float qx = 0.f, qy = 0.f, qz = 0.f, qw = 0.f;
    #pragma unroll 8
    for (int i = tid; i < B_SZ / 4; i += 256) {
        float4 v = col[i];
        ax += v.x; ay += v.y; az += v.z; aw += v.w;
        qx = fmaf(v.x, v.x, qx); qy = fmaf(v.y, v.y, qy);
        qz = fmaf(v.z, v.z, qz); qw = fmaf(v.w, v.w, qw);
    }
    double a1 = (double)ax + (double)ay + (double)az + (double)aw;
    double a2 = (double)qx + (double)qy + (double)qz + (double)qw;
    __shared__ double s1[256], s2[256];
    s1[tid] = a1; s2[tid] = a2;
    __syncthreads();
    for (int o = 128; o > 0; o >>= 1) {
        if (tid < o) { s1[tid] += s1[tid + o]; s2[tid] += s2[tid + o]; }
        __syncthreads();
    }
    if (tid == 0) { g_S1[p] = s1[0]; g_S2[p] = s2[0]; }
}

// ============ K3: per-block BN/L2/projection finalize + out[b] = sigmoid(dot + c) ============
__global__ __launch_bounds__(256) void k3_out(float* __restrict__ out,
                                              const float* __restrict__ gamma,
                                              const float* __restrict__ beta,
                                              const float* __restrict__ Wd,
                                              const float* __restrict__ bdp) {
    __shared__ float sa[128];
    __shared__ float sw[128];
    __shared__ float sn[128], st[128];
    __shared__ float sc_s;
    const int tid = threadIdx.x;

    if (tid < 128) {
        const int p = tid;
        const double invB = 1.0 / (double)B_SZ;
        double mean_d = g_S1[p] * invB;
        double var_d = g_S2[p] * invB - mean_d * mean_d;   // fp64: cancellation-sensitive
        float var = (float)(var_d < 0.0 ? 0.0 : var_d);
        float mean = (float)mean_d;
        float sig2 = var + (float)BN_EPS;
        float inv_sigma = rsqrtf(sig2);
        float g = gamma[p], bt = beta[p], wd = Wd[p];
        sn[p] = g * g * (float)B_SZ * var / sig2 + (float)B_SZ * bt * bt;
        st[p] = (bt - mean * g * inv_sigma) * wd;
        sw[p] = g * wd * inv_sigma;
    }
    __syncthreads();
    for (int o = 64; o > 0; o >>= 1) {
        if (tid < o) { sn[tid] += sn[tid + o]; st[tid] += st[tid + o]; }
        __syncthreads();
    }
    if (tid < 128) {
        float inv_norm = rsqrtf(sn[0]);
        sa[tid] = sw[tid] * inv_norm;
        if (tid == 0) sc_s = st[0] * inv_norm + bdp[0];
    }
    __syncthreads();
    const float sc = sc_s;

    const int gid = blockIdx.x * 256 + tid;
    const int q = gid & 31;                // pathway chunk (4 pathways)
    const int t = gid >> 5;                // float4 index over b (0..4095)
    const float4* pp = reinterpret_cast<const float4*>(g_p);

    float4 acc = make_float4(0.f, 0.f, 0.f, 0.f);
    #pragma unroll
    for (int i = 0; i < 4; i++) {
        int p = q * 4 + i;
        float4 v = pp[(size_t)p * (B_SZ / 4) + t];
        float a = sa[p];
        acc.x += v.x * a; acc.y += v.y * a; acc.z += v.z * a; acc.w += v.w * a;
    }
    #pragma unroll
    for (int m = 1; m < 32; m <<= 1) {
        acc.x += __shfl_xor_sync(0xFFFFFFFF, acc.x, m);
        acc.y += __shfl_xor_sync(0xFFFFFFFF, acc.y, m);
        acc.z += __shfl_xor_sync(0xFFFFFFFF, acc.z, m);
        acc.w += __shfl_xor_sync(0xFFFFFFFF, acc.w, m);
    }
    if (q == 0) {
        float4 o;
        o.x = 1.f / (1.f + expf(-(acc.x + sc)));
        o.y = 1.f / (1.f + expf(-(acc.y + sc)));
        o.z = 1.f / (1.f + expf(-(acc.z + sc)));
        o.w = 1.f / (1.f + expf(-(acc.w + sc)));
        reinterpret_cast<float4*>(out)[t] = o;
    }
}

// ============ launch ============
extern "C" void kernel_launch(void* const* d_in, const int* in_sizes, int n_in,
                              void* d_out, int out_size) {
    const float* x     = (const float*)d_in[0];
    const float* W1    = (const float*)d_in[1];
    const float* W2    = (const float*)d_in[2];
    const float* gamma = (const float*)d_in[3];
    const float* beta  = (const float*)d_in[4];
    const float* Wd    = (const float*)d_in[5];
    const float* bdp   = (const float*)d_in[6];
    float* out = (float*)d_out;

    k0_w1bf<<<1024, 256>>>(W1);
    k1_mma<<<dim3(B_SZ / 128, P_N), 128, 49152>>>(x, W2);
    k2a_reduce<<<P_N, 256>>>();
    k3_out<<<512, 256>>>(out, gamma, beta, Wd, bdp);
}

// round 10
// speedup vs baseline: 1.1484x; 1.0033x over previous
#include <cuda_runtime.h>
#include <cuda_bf16.h>
#include <cstdint>

// ---------------- problem constants ----------------
#define B_SZ 16384
#define P_N  128
#define V_N  128
#define W_N  64
#define BN_EPS 1e-5

// ---------------- scratch (static device globals; no allocation) ----------------
__device__ float          g_p[P_N * B_SZ];          // p[pathway][batch], 8 MB
__device__ __nv_bfloat16  g_W1bf[P_N * W_N * V_N];  // bf16 W1, row-major [p][w][v], 2 MB
__device__ double         g_S1[P_N], g_S2[P_N];

__device__ __forceinline__ uint32_t smem_u32(const void* p) {
    uint32_t a;
    asm("{ .reg .u64 t; cvta.to.shared.u64 t, %1; cvt.u32.u64 %0, t; }" : "=r"(a) : "l"(p));
    return a;
}

// swizzled byte offset inside a [rows][128 bf16] tile (256 B per row)
__device__ __forceinline__ int swz(int row, int byte_in_row) {
    return row * 256 + (byte_in_row ^ ((row & 7) << 4));
}

__device__ __forceinline__ void ldmatrix_x4(uint32_t& r0, uint32_t& r1, uint32_t& r2, uint32_t& r3,
                                            uint32_t addr) {
    asm volatile("ldmatrix.sync.aligned.m8n8.x4.shared.b16 {%0,%1,%2,%3}, [%4];"
                 : "=r"(r0), "=r"(r1), "=r"(r2), "=r"(r3) : "r"(addr));
}

__device__ __forceinline__ void mma_bf16(float& c0, float& c1, float& c2, float& c3,
                                         uint32_t a0, uint32_t a1, uint32_t a2, uint32_t a3,
                                         uint32_t b0, uint32_t b1) {
    asm volatile("mma.sync.aligned.m16n8k16.row.col.f32.bf16.bf16.f32 "
                 "{%0,%1,%2,%3}, {%4,%5,%6,%7}, {%8,%9}, {%0,%1,%2,%3};"
                 : "+f"(c0), "+f"(c1), "+f"(c2), "+f"(c3)
                 : "r"(a0), "r"(a1), "r"(a2), "r"(a3), "r"(b0), "r"(b1));
}

// ============ K0: convert W1 fp32 -> bf16 row-major ============
__global__ __launch_bounds__(256) void k0_w1bf(const float* __restrict__ W1) {
    int idx = blockIdx.x * 256 + threadIdx.x;      // < 262144, each handles 4 elems
    float4 v = *reinterpret_cast<const float4*>(W1 + (size_t)idx * 4);
    __nv_bfloat162 lo = __float22bfloat162_rn(make_float2(v.x, v.y));
    __nv_bfloat162 hi = __float22bfloat162_rn(make_float2(v.z, v.w));
    uint2 pack = make_uint2(*reinterpret_cast<uint32_t*>(&lo), *reinterpret_cast<uint32_t*>(&hi));
    *reinterpret_cast<uint2*>(g_W1bf + (size_t)idx * 4) = pack;
}

// ============ K1: per-pathway [128x64x128] bf16 mma.sync, 4 warps x (32x64) tiles ============
// (byte-identical to R9)
__global__ __launch_bounds__(128, 4) void k1_mma(const float* __restrict__ x,
                                                 const float* __restrict__ W2) {
    extern __shared__ char smem[];                 // [0,32768) xs swizzled, [32768,49152) ws swizzled
    const uint32_t sb = smem_u32(smem);
    const int tid = threadIdx.x;
    const int wid = tid >> 5;
    const int lid = tid & 31;
    const int rb = blockIdx.x;                     // 128-row batch block
    const int p  = blockIdx.y;                     // pathway

    // ---- load + convert x tile: 128 rows x 128 fp32 -> bf16 swizzled smem ----
    {
        const float* xrow = x + (size_t)rb * 128 * (P_N * V_N) + (size_t)p * V_N;
        #pragma unroll
        for (int i = 0; i < 32; i++) {
            int idx = tid + i * 128;               // < 4096
            int r = idx >> 5;
            int c = (idx & 31);                    // float4 index in row
            float4 v = *reinterpret_cast<const float4*>(xrow + (size_t)r * (P_N * V_N) + c * 4);
            __nv_bfloat162 lo = __float22bfloat162_rn(make_float2(v.x, v.y));
            __nv_bfloat162 hi = __float22bfloat162_rn(make_float2(v.z, v.w));
            uint2 pack = make_uint2(*reinterpret_cast<uint32_t*>(&lo), *reinterpret_cast<uint32_t*>(&hi));
            *reinterpret_cast<uint2*>(smem + swz(r, c * 8)) = pack;
        }
    }
    // ---- copy W1 bf16 tile: 64 rows x 128 -> swizzled smem ----
    {
        const uint4* wsrc = reinterpret_cast<const uint4*>(g_W1bf + (size_t)p * (W_N * V_N));
        #pragma unroll
        for (int i = 0; i < 8; i++) {
            int idx = tid + i * 128;               // < 1024 16B-chunks
            int n = idx >> 4;
            int kc = idx & 15;
            *reinterpret_cast<uint4*>(smem + 32768 + swz(n, kc * 16)) = wsrc[idx];
        }
    }
    __syncthreads();

    // ---- mainloop: warp computes [32 x 64], K=128 ----
    float acc[2][8][4];                             // [m16-frag][n8-frag][quad]
    #pragma unroll
    for (int m = 0; m < 2; m++)
        #pragma unroll
        for (int t = 0; t < 8; t++)
            #pragma unroll
            for (int j = 0; j < 4; j++) acc[m][t][j] = 0.f;

    const int m0 = wid * 32;
    const uint32_t a_row = m0 + (lid & 15);
    const uint32_t a_chunk = (lid >> 4) * 16;
    const int bg = lid >> 3;                        // 0..3 address group
    const int b_nrow_off = (lid & 7) + ((bg >= 2) ? 8 : 0);
    const int b_koff = (bg & 1) * 16;

    #pragma unroll
    for (int ks = 0; ks < 8; ks++) {
        const int kb = ks * 32;                     // byte offset of k-step in row
        uint32_t a00, a01, a02, a03;                // rows [m0, m0+16)
        uint32_t a10, a11, a12, a13;                // rows [m0+16, m0+32)
        ldmatrix_x4(a00, a01, a02, a03, sb + swz(a_row, kb + a_chunk));
        ldmatrix_x4(a10, a11, a12, a13, sb + swz(a_row + 16, kb + a_chunk));
        #pragma unroll
        for (int t = 0; t < 4; t++) {
            uint32_t b0, b1, b2, b3;
            ldmatrix_x4(b0, b1, b2, b3,
                        sb + 32768 + swz(t * 16 + b_nrow_off, kb + b_koff));
            mma_bf16(acc[0][2*t][0], acc[0][2*t][1], acc[0][2*t][2], acc[0][2*t][3],
                     a00, a01, a02, a03, b0, b1);
            mma_bf16(acc[0][2*t+1][0], acc[0][2*t+1][1], acc[0][2*t+1][2], acc[0][2*t+1][3],
                     a00, a01, a02, a03, b2, b3);
            mma_bf16(acc[1][2*t][0], acc[1][2*t][1], acc[1][2*t][2], acc[1][2*t][3],
                     a10, a11, a12, a13, b0, b1);
            mma_bf16(acc[1][2*t+1][0], acc[1][2*t+1][1], acc[1][2*t+1][2], acc[1][2*t+1][3],
                     a10, a11, a12, a13, b2, b3);
        }
    }

    // ---- epilogue: h=leaky(acc); dot with W2 over n; p=leaky(dot) ----
    {
        const float2* w2p = reinterpret_cast<const float2*>(W2 + (size_t)p * W_N);
        float s00 = 0.f, s01 = 0.f;                 // m-frag 0: rows (lid>>2), (lid>>2)+8
        float s10 = 0.f, s11 = 0.f;                 // m-frag 1: +16
        #pragma unroll
        for (int t = 0; t < 8; t++) {
            float2 w2v = __ldg(&w2p[t * 4 + (lid & 3)]);   // cols t*8 + (lid&3)*2, +1
            float h;
            h = acc[0][t][0]; h = (h >= 0.f) ? h : 0.2f * h; s00 += h * w2v.x;
            h = acc[0][t][1]; h = (h >= 0.f) ? h : 0.2f * h; s00 += h * w2v.y;
            h = acc[0][t][2]; h = (h >= 0.f) ? h : 0.2f * h; s01 += h * w2v.x;
            h = acc[0][t][3]; h = (h >= 0.f) ? h : 0.2f * h; s01 += h * w2v.y;
            h = acc[1][t][0]; h = (h >= 0.f) ? h : 0.2f * h; s10 += h * w2v.x;
            h = acc[1][t][1]; h = (h >= 0.f) ? h : 0.2f * h; s10 += h * w2v.y;
            h = acc[1][t][2]; h = (h >= 0.f) ? h : 0.2f * h; s11 += h * w2v.x;
            h = acc[1][t][3]; h = (h >= 0.f) ? h : 0.2f * h; s11 += h * w2v.y;
        }
        s00 += __shfl_xor_sync(0xFFFFFFFF, s00, 1);
        s00 += __shfl_xor_sync(0xFFFFFFFF, s00, 2);
        s01 += __shfl_xor_sync(0xFFFFFFFF, s01, 1);
        s01 += __shfl_xor_sync(0xFFFFFFFF, s01, 2);
        s10 += __shfl_xor_sync(0xFFFFFFFF, s10, 1);
        s10 += __shfl_xor_sync(0xFFFFFFFF, s10, 2);
        s11 += __shfl_xor_sync(0xFFFFFFFF, s11, 1);
        s11 += __shfl_xor_sync(0xFFFFFFFF, s11, 2);
        if ((lid & 3) == 0) {
            int row = lid >> 2;
            float pv00 = (s00 >= 0.f) ? s00 : 0.2f * s00;
            float pv01 = (s01 >= 0.f) ? s01 : 0.2f * s01;
            float pv10 = (s10 >= 0.f) ? s10 : 0.2f * s10;
            float pv11 = (s11 >= 0.f) ? s11 : 0.2f * s11;
            float* dst = g_p + (size_t)p * B_SZ + rb * 128 + m0;
            dst[row] = pv00;
            dst[row + 8] = pv01;
            dst[row + 16] = pv10;
            dst[row + 24] = pv11;
        }
    }
}

// ============ K2a: per-pathway sum / sumsq (fp32 lane accumulators, fp64 tree) ============
__global__ __launch_bounds__(256) void k2a_reduce() {
    const int p = blockIdx.x;
    const int tid = threadIdx.x;
    const float4* col = reinterpret_cast<const float4*>(g_p + (size_t)p * B_SZ);
    float ax = 0.f, ay = 0.f, az = 0.f, aw = 0.f;
    float qx = 0.f, qy = 0.f, qz = 0.f, qw = 0.f;
    #pragma unroll 8
    for (int i = tid; i < B_SZ / 4; i += 256) {
        float4 v = col[i];
        ax += v.x; ay += v.y; az += v.z; aw += v.w;
        qx = fmaf(v.x, v.x, qx); qy = fmaf(v.y, v.y, qy);
        qz = fmaf(v.z, v.z, qz); qw = fmaf(v.w, v.w, qw);
    }
    double a1 = (double)ax + (double)ay + (double)az + (double)aw;
    double a2 = (double)qx + (double)qy + (double)qz + (double)qw;
    __shared__ double s1[256], s2[256];
    s1[tid] = a1; s2[tid] = a2;
    __syncthreads();
    for (int o = 128; o > 0; o >>= 1) {
        if (tid < o) { s1[tid] += s1[tid + o]; s2[tid] += s2[tid + o]; }
        __syncthreads();
    }
    if (tid == 0) { g_S1[p] = s1[0]; g_S2[p] = s2[0]; }
}

// ============ K3: hoisted g_p loads + per-block finalize + sigmoid(dot + c) ============
// The 4 independent LDG.128s are issued BEFORE the barrier-heavy finalize so their
// ~600-cycle DRAM latency overlaps the coefficient computation.
__global__ __launch_bounds__(256) void k3_out(float* __restrict__ out,
                                              const float* __restrict__ gamma,
                                              const float* __restrict__ beta,
                                              const float* __restrict__ Wd,
                                              const float* __restrict__ bdp) {
    __shared__ float sa[128];
    __shared__ float sw[128];
    __shared__ float sn[128], st[128];
    __shared__ float sc_s;
    const int tid = threadIdx.x;

    // ---- issue data loads first (independent of coefficients) ----
    const int gid = blockIdx.x * 256 + tid;
    const int q = gid & 31;                // pathway chunk (4 pathways)
    const int t = gid >> 5;                // float4 index over b (0..4095)
    const float4* pp = reinterpret_cast<const float4*>(g_p);
    float4 v0 = pp[(size_t)(q * 4 + 0) * (B_SZ / 4) + t];
    float4 v1 = pp[(size_t)(q * 4 + 1) * (B_SZ / 4) + t];
    float4 v2 = pp[(size_t)(q * 4 + 2) * (B_SZ / 4) + t];
    float4 v3 = pp[(size_t)(q * 4 + 3) * (B_SZ / 4) + t];

    // ---- in-block finalize (threads 0..127) while loads are in flight ----
    if (tid < 128) {
        const int p = tid;
        const double invB = 1.0 / (double)B_SZ;
        double mean_d = g_S1[p] * invB;
        double var_d = g_S2[p] * invB - mean_d * mean_d;   // fp64: cancellation-sensitive
        float var = (float)(var_d < 0.0 ? 0.0 : var_d);
        float mean = (float)mean_d;
        float sig2 = var + (float)BN_EPS;
        float inv_sigma = rsqrtf(sig2);
        float g = gamma[p], bt = beta[p], wd = Wd[p];
        sn[p] = g * g * (float)B_SZ * var / sig2 + (float)B_SZ * bt * bt;
        st[p] = (bt - mean * g * inv_sigma) * wd;
        sw[p] = g * wd * inv_sigma;
    }
    __syncthreads();
    for (int o = 64; o > 0; o >>= 1) {
        if (tid < o) { sn[tid] += sn[tid + o]; st[tid] += st[tid + o]; }
        __syncthreads();
    }
    if (tid < 128) {
        float inv_norm = rsqrtf(sn[0]);
        sa[tid] = sw[tid] * inv_norm;
        if (tid == 0) sc_s = st[0] * inv_norm + bdp[0];
    }
    __syncthreads();
    const float sc = sc_s;

    // ---- dot + butterfly + sigmoid ----
    float a0 = sa[q * 4 + 0], a1 = sa[q * 4 + 1], a2 = sa[q * 4 + 2], a3 = sa[q * 4 + 3];
    float4 acc;
    acc.x = v0.x * a0 + v1.x * a1 + v2.x * a2 + v3.x * a3;
    acc.y = v0.y * a0 + v1.y * a1 + v2.y * a2 + v3.y * a3;
    acc.z = v0.z * a0 + v1.z * a1 + v2.z * a2 + v3.z * a3;
    acc.w = v0.w * a0 + v1.w * a1 + v2.w * a2 + v3.w * a3;
    #pragma unroll
    for (int m = 1; m < 32; m <<= 1) {
        acc.x += __shfl_xor_sync(0xFFFFFFFF, acc.x, m);
        acc.y += __shfl_xor_sync(0xFFFFFFFF, acc.y, m);
        acc.z += __shfl_xor_sync(0xFFFFFFFF, acc.z, m);
        acc.w += __shfl_xor_sync(0xFFFFFFFF, acc.w, m);
    }
    if (q == 0) {
        float4 o;
        o.x = 1.f / (1.f + expf(-(acc.x + sc)));
        o.y = 1.f / (1.f + expf(-(acc.y + sc)));
        o.z = 1.f / (1.f + expf(-(acc.z + sc)));
        o.w = 1.f / (1.f + expf(-(acc.w + sc)));
        reinterpret_cast<float4*>(out)[t] = o;
    }
}

// ============ launch ============
extern "C" void kernel_launch(void* const* d_in, const int* in_sizes, int n_in,
                              void* d_out, int out_size) {
    const float* x     = (const float*)d_in[0];
    const float* W1    = (const float*)d_in[1];
    const float* W2    = (const float*)d_in[2];
    const float* gamma = (const float*)d_in[3];
    const float* beta  = (const float*)d_in[4];
    const float* Wd    = (const float*)d_in[5];
    const float* bdp   = (const float*)d_in[6];
    float* out = (float*)d_out;

    k0_w1bf<<<1024, 256>>>(W1);
    k1_mma<<<dim3(B_SZ / 128, P_N), 128, 49152>>>(x, W2);
    k2a_reduce<<<P_N, 256>>>();
    k3_out<<<512, 256>>>(out, gamma, beta, Wd, bdp);
}